// round 2
// baseline (speedup 1.0000x reference)
#include <cuda_runtime.h>
#include <math.h>

// Problem constants (fixed by the dataset)
#define NN   50000
#define EE   800000
#define NINF 256
#define HH   8
#define CCH  32
#define HC   256

// ---------------- device scratch (allocation-free: static globals) ----------
__device__ float g_q[(size_t)NN * HC];          // 51.2 MB
__device__ float g_k[(size_t)NN * HC];          // 51.2 MB
__device__ float g_v[(size_t)NN * HC];          // 51.2 MB
__device__ float g_e[(size_t)EE * HC];          // 819.2 MB (edge features, dst-sorted)
__device__ int   g_deg[NN];
__device__ int   g_off[NN + 1];
__device__ int   g_cur[NN];
__device__ int   g_srcs[EE];                    // src node of sorted edge
__device__ int   g_perm[EE];                    // sorted position -> original edge id
__device__ int   g_is64;                        // 1 if edge_index is int64, 0 if int32

// ---------------- dtype sniffer ---------------------------------------------
// If edge_index is int32 but read as int64, entries pack two random node ids:
// value = lo + hi*2^32 >= 2^32 unless hi==0 (p = 1/50000 per entry). Checking
// 64 entries makes misdetection probability ~0.
__global__ void k_detect(const long long* __restrict__ ei) {
    if (threadIdx.x == 0 && blockIdx.x == 0) {
        int ok = 1;
        for (int i = 0; i < 64; i++) {
            long long v = ei[i];
            if (v < 0 || v >= NN) ok = 0;
        }
        g_is64 = ok;
    }
}

__device__ __forceinline__ int load_idx(const void* ei, size_t pos, int is64) {
    if (is64) return (int)((const long long*)ei)[pos];
    return ((const int*)ei)[pos];
}

// ---------------- counting sort by destination ------------------------------
__global__ void k_zero_deg() {
    int i = blockIdx.x * blockDim.x + threadIdx.x;
    if (i < NN) g_deg[i] = 0;
}

__global__ void k_hist(const void* __restrict__ ei) {
    int e = blockIdx.x * blockDim.x + threadIdx.x;
    if (e < EE) {
        int d = load_idx(ei, (size_t)EE + e, g_is64);
        if ((unsigned)d < NN) atomicAdd(&g_deg[d], 1);
    }
}

// single-block scan over g_deg -> g_off (exclusive prefix in g_cur)
__global__ void k_scan() {
    __shared__ int sh[1024];
    __shared__ int carry_s;
    int t = threadIdx.x;
    if (t == 0) carry_s = 0;
    __syncthreads();
    for (int base = 0; base < NN; base += 1024) {
        int i = base + t;
        int v = (i < NN) ? g_deg[i] : 0;
        sh[t] = v;
        __syncthreads();
        #pragma unroll
        for (int off = 1; off < 1024; off <<= 1) {
            int add = (t >= off) ? sh[t - off] : 0;
            __syncthreads();
            sh[t] += add;
            __syncthreads();
        }
        int incl  = sh[t];
        int carry = carry_s;
        if (i < NN) {
            g_off[i + 1] = carry + incl;
            g_cur[i]     = carry + incl - v;   // exclusive prefix = write cursor
        }
        __syncthreads();
        if (t == 1023) carry_s = carry + incl;
        __syncthreads();
    }
    if (t == 0) g_off[0] = 0;
}

__global__ void k_scatter(const void* __restrict__ ei) {
    int e = blockIdx.x * blockDim.x + threadIdx.x;
    if (e < EE) {
        int is64 = g_is64;
        int d = load_idx(ei, (size_t)EE + e, is64);
        int s = load_idx(ei, (size_t)e, is64);
        if ((unsigned)d < NN && (unsigned)s < NN) {
            int pos = atomicAdd(&g_cur[d], 1);
            if ((unsigned)pos < EE) {
                g_perm[pos] = e;
                g_srcs[pos] = s;
            }
        }
    }
}

// ---------------- fp32 SGEMM 128x128x16, 8x8 register blocking --------------
// C[M,256] = A[M,256] @ B[256,256] (+ bias). GATHER: A rows indexed via g_perm.
// which: 0->g_q 1->g_k 2->g_v 3->d_out 4->g_e
template <bool GATHER>
__global__ __launch_bounds__(256, 2)
void k_sgemm(const float* __restrict__ A, const float* __restrict__ B,
             const float* __restrict__ bias, float* __restrict__ dout,
             int which, int M) {
    float* Cout;
    switch (which) {
        case 0: Cout = g_q; break;
        case 1: Cout = g_k; break;
        case 2: Cout = g_v; break;
        case 3: Cout = dout; break;
        default: Cout = g_e; break;
    }

    __shared__ float As[16][128];
    __shared__ float Bs[16][128];

    int t  = threadIdx.x;
    int bm = blockIdx.x * 128;
    int bn = blockIdx.y * 128;
    int tx = t & 15, ty = t >> 4;

    float acc[8][8];
    #pragma unroll
    for (int i = 0; i < 8; i++)
        #pragma unroll
        for (int j = 0; j < 8; j++) acc[i][j] = 0.f;

    int ar = t >> 2,  ac = (t & 3) * 4;     // A tile: 128 rows x 16 cols
    int bk = t >> 5,  bc = (t & 31) * 4;    // B tile: 16 rows x 128 cols

    for (int k0 = 0; k0 < 256; k0 += 16) {
        #pragma unroll
        for (int i = 0; i < 2; i++) {
            int row = bm + ar + i * 64;
            int rr  = (row < M) ? row : (M - 1);
            int grow = GATHER ? g_perm[rr] : rr;
            float4 a = *(const float4*)(A + (size_t)grow * 256 + k0 + ac);
            As[ac + 0][ar + i * 64] = a.x;
            As[ac + 1][ar + i * 64] = a.y;
            As[ac + 2][ar + i * 64] = a.z;
            As[ac + 3][ar + i * 64] = a.w;
        }
        #pragma unroll
        for (int i = 0; i < 2; i++) {
            float4 b = *(const float4*)(B + (size_t)(k0 + bk + i * 8) * 256 + bn + bc);
            *(float4*)&Bs[bk + i * 8][bc] = b;
        }
        __syncthreads();
        #pragma unroll
        for (int kk = 0; kk < 16; kk++) {
            float ra[8], rb[8];
            *(float4*)(ra)     = *(float4*)&As[kk][ty * 8];
            *(float4*)(ra + 4) = *(float4*)&As[kk][ty * 8 + 4];
            *(float4*)(rb)     = *(float4*)&Bs[kk][tx * 8];
            *(float4*)(rb + 4) = *(float4*)&Bs[kk][tx * 8 + 4];
            #pragma unroll
            for (int i = 0; i < 8; i++)
                #pragma unroll
                for (int j = 0; j < 8; j++)
                    acc[i][j] = fmaf(ra[i], rb[j], acc[i][j]);
        }
        __syncthreads();
    }

    float bb[8];
    #pragma unroll
    for (int j = 0; j < 8; j++) bb[j] = bias ? bias[bn + tx * 8 + j] : 0.f;

    #pragma unroll
    for (int i = 0; i < 8; i++) {
        int row = bm + ty * 8 + i;
        if (row < M) {
            float* cptr = Cout + (size_t)row * 256 + bn + tx * 8;
            float4 o0, o1;
            o0.x = acc[i][0] + bb[0]; o0.y = acc[i][1] + bb[1];
            o0.z = acc[i][2] + bb[2]; o0.w = acc[i][3] + bb[3];
            o1.x = acc[i][4] + bb[4]; o1.y = acc[i][5] + bb[5];
            o1.z = acc[i][6] + bb[6]; o1.w = acc[i][7] + bb[7];
            *(float4*)(cptr)     = o0;
            *(float4*)(cptr + 4) = o1;
        }
    }
}

// ---------------- attention: warp per (node, head), online softmax ----------
__global__ __launch_bounds__(256)
void k_aggregate(float* __restrict__ out) {
    int n    = blockIdx.x;
    int h    = threadIdx.x >> 5;
    int lane = threadIdx.x & 31;

    int begin = g_off[n], end = g_off[n + 1];
    size_t qi = (size_t)n * HC + h * CCH + lane;
    float qv  = g_q[qi] * 0.17677669529663687f;   // 1/sqrt(C)

    float m = -INFINITY, l = 0.f, acc = 0.f;

    for (int idx = begin; idx < end; idx++) {
        int src  = g_srcs[idx];
        float ec = __ldcs(&g_e[(size_t)idx * HC + h * CCH + lane]);
        size_t kb = (size_t)src * HC + h * CCH + lane;
        float kj = g_k[kb] + ec;
        float s  = qv * kj;
        #pragma unroll
        for (int o = 16; o; o >>= 1) s += __shfl_xor_sync(0xffffffffu, s, o);

        float nm = fmaxf(m, s);
        float cf = __expf(m - nm);
        float p  = __expf(s - nm);
        l   = l * cf + p;
        float vj = g_v[kb] + ec;
        acc = acc * cf + p * vj;
        m   = nm;
    }
    if (l > 0.f) out[qi] += acc / l;
}

// ---------------- launch ----------------------------------------------------
extern "C" void kernel_launch(void* const* d_in, const int* in_sizes, int n_in,
                              void* d_out, int out_size) {
    const float* x  = (const float*)d_in[0];
    const void*  ei = d_in[1];
    const float* ea = (const float*)d_in[2];
    const float* Wq = (const float*)d_in[3];
    const float* bq = (const float*)d_in[4];
    const float* Wk = (const float*)d_in[5];
    const float* bk = (const float*)d_in[6];
    const float* Wv = (const float*)d_in[7];
    const float* bv = (const float*)d_in[8];
    const float* We = (const float*)d_in[9];
    const float* Ws = (const float*)d_in[10];
    const float* bs = (const float*)d_in[11];
    float* out = (float*)d_out;

    // 0) sniff edge_index dtype (int64 vs int32)
    k_detect<<<1, 32>>>((const long long*)ei);

    // 1) sort edges by destination (CSR build)
    k_zero_deg<<<(NN + 255) / 256, 256>>>();
    k_hist<<<(EE + 255) / 256, 256>>>(ei);
    k_scan<<<1, 1024>>>();
    k_scatter<<<(EE + 255) / 256, 256>>>(ei);

    // 2) node GEMMs: q, k, v, and skip (x@Ws+bs) written straight into out
    dim3 gn((NN + 127) / 128, 2);
    k_sgemm<false><<<gn, 256>>>(x, Wq, bq, out, 0, NN);
    k_sgemm<false><<<gn, 256>>>(x, Wk, bk, out, 1, NN);
    k_sgemm<false><<<gn, 256>>>(x, Wv, bv, out, 2, NN);
    k_sgemm<false><<<gn, 256>>>(x, Ws, bs, out, 3, NN);

    // 3) edge GEMM, rows gathered through perm so g_e lands dst-sorted
    dim3 ge(EE / 128, 2);
    k_sgemm<true><<<ge, 256>>>(ea, We, nullptr, out, 4, EE);

    // 4) attention with online softmax, no atomics, adds onto skip
    k_aggregate<<<NN, 256>>>(out);
}

// round 3
// speedup vs baseline: 1.3503x; 1.3503x over previous
#include <cuda_runtime.h>
#include <math.h>

// Problem constants (fixed by the dataset)
#define NN   50000
#define EE   800000
#define HH   8
#define CCH  32
#define HC   256
#define NB_SCAN 49   // ceil(NN/1024)

// ---------------- device scratch (allocation-free: static globals) ----------
__device__ float g_q[(size_t)NN * HC];              // 51.2 MB
__device__ float g_k[(size_t)NN * HC];              // 51.2 MB
__device__ float g_v[(size_t)NN * HC];              // 51.2 MB
__device__ float g_P[(size_t)NN * HH * 256];        // 409.6 MB  P[n,h,i]
__device__ float g_A[(size_t)NN * HH * 256];        // 409.6 MB  A[n,h,i] (alpha-weighted ea)
__device__ int   g_deg[NN];
__device__ int   g_off[NN + 1];
__device__ int   g_cur[NN];
__device__ int   g_incl[NN];
__device__ int   g_bsum[64];
__device__ int   g_bpre[64];
__device__ int   g_srcs[EE];
__device__ int   g_perm[EE];                        // sorted position -> original edge id
__device__ int   g_is64;

// ---------------- dtype sniffer ---------------------------------------------
__global__ void k_detect(const long long* __restrict__ ei) {
    if (threadIdx.x == 0 && blockIdx.x == 0) {
        int ok = 1;
        for (int i = 0; i < 64; i++) {
            long long v = ei[i];
            if (v < 0 || v >= NN) ok = 0;
        }
        g_is64 = ok;
    }
}

__device__ __forceinline__ int load_idx(const void* ei, size_t pos, int is64) {
    if (is64) return (int)((const long long*)ei)[pos];
    return ((const int*)ei)[pos];
}

// ---------------- counting sort by destination ------------------------------
__global__ void k_zero_deg() {
    int i = blockIdx.x * blockDim.x + threadIdx.x;
    if (i < NN) g_deg[i] = 0;
}

__global__ void k_hist(const void* __restrict__ ei) {
    int e = blockIdx.x * blockDim.x + threadIdx.x;
    if (e < EE) {
        int d = load_idx(ei, (size_t)EE + e, g_is64);
        if ((unsigned)d < NN) atomicAdd(&g_deg[d], 1);
    }
}

// 3-phase scan: per-block inclusive scans, scan of block sums, add-back.
__global__ void k_scan1() {
    __shared__ int sh[1024];
    int t = threadIdx.x;
    int i = blockIdx.x * 1024 + t;
    int v = (i < NN) ? g_deg[i] : 0;
    sh[t] = v;
    __syncthreads();
    #pragma unroll
    for (int off = 1; off < 1024; off <<= 1) {
        int add = (t >= off) ? sh[t - off] : 0;
        __syncthreads();
        sh[t] += add;
        __syncthreads();
    }
    if (i < NN) g_incl[i] = sh[t];
    if (t == 1023) g_bsum[blockIdx.x] = sh[t];
}

__global__ void k_scan2() {
    if (threadIdx.x == 0) {
        int run = 0;
        for (int b = 0; b < NB_SCAN; b++) {
            g_bpre[b] = run;
            run += g_bsum[b];
        }
    }
}

__global__ void k_scan3() {
    int i = blockIdx.x * blockDim.x + threadIdx.x;
    if (i < NN) {
        int incl = g_incl[i] + g_bpre[i >> 10];
        g_off[i + 1] = incl;
        g_cur[i]     = incl - g_deg[i];
    }
    if (i == 0) g_off[0] = 0;
}

__global__ void k_scatter(const void* __restrict__ ei) {
    int e = blockIdx.x * blockDim.x + threadIdx.x;
    if (e < EE) {
        int is64 = g_is64;
        int d = load_idx(ei, (size_t)EE + e, is64);
        int s = load_idx(ei, (size_t)e, is64);
        if ((unsigned)d < NN && (unsigned)s < NN) {
            int pos = atomicAdd(&g_cur[d], 1);
            if ((unsigned)pos < EE) {
                g_perm[pos] = e;
                g_srcs[pos] = s;
            }
        }
    }
}

// ---------------- fp32 SGEMM 128x128x16, 8x8 register blocking --------------
// C[M,256] = A[M,256] @ B[256,256] + bias.  which: 0->g_q 1->g_k 2->g_v 3->out
__global__ __launch_bounds__(256, 2)
void k_sgemm(const float* __restrict__ A, const float* __restrict__ B,
             const float* __restrict__ bias, float* __restrict__ dout,
             int which, int M) {
    float* Cout;
    switch (which) {
        case 0: Cout = g_q; break;
        case 1: Cout = g_k; break;
        case 2: Cout = g_v; break;
        default: Cout = dout; break;
    }

    __shared__ float As[16][128];
    __shared__ float Bs[16][128];

    int t  = threadIdx.x;
    int bm = blockIdx.x * 128;
    int bn = blockIdx.y * 128;
    int tx = t & 15, ty = t >> 4;

    float acc[8][8];
    #pragma unroll
    for (int i = 0; i < 8; i++)
        #pragma unroll
        for (int j = 0; j < 8; j++) acc[i][j] = 0.f;

    int ar = t >> 2,  ac = (t & 3) * 4;
    int bk = t >> 5,  bc = (t & 31) * 4;

    for (int k0 = 0; k0 < 256; k0 += 16) {
        #pragma unroll
        for (int i = 0; i < 2; i++) {
            int row = bm + ar + i * 64;
            int rr  = (row < M) ? row : (M - 1);
            float4 a = *(const float4*)(A + (size_t)rr * 256 + k0 + ac);
            As[ac + 0][ar + i * 64] = a.x;
            As[ac + 1][ar + i * 64] = a.y;
            As[ac + 2][ar + i * 64] = a.z;
            As[ac + 3][ar + i * 64] = a.w;
        }
        #pragma unroll
        for (int i = 0; i < 2; i++) {
            float4 b = *(const float4*)(B + (size_t)(k0 + bk + i * 8) * 256 + bn + bc);
            *(float4*)&Bs[bk + i * 8][bc] = b;
        }
        __syncthreads();
        #pragma unroll
        for (int kk = 0; kk < 16; kk++) {
            float ra[8], rb[8];
            *(float4*)(ra)     = *(float4*)&As[kk][ty * 8];
            *(float4*)(ra + 4) = *(float4*)&As[kk][ty * 8 + 4];
            *(float4*)(rb)     = *(float4*)&Bs[kk][tx * 8];
            *(float4*)(rb + 4) = *(float4*)&Bs[kk][tx * 8 + 4];
            #pragma unroll
            for (int i = 0; i < 8; i++)
                #pragma unroll
                for (int j = 0; j < 8; j++)
                    acc[i][j] = fmaf(ra[i], rb[j], acc[i][j]);
        }
        __syncthreads();
    }

    float bb[8];
    #pragma unroll
    for (int j = 0; j < 8; j++) bb[j] = bias[bn + tx * 8 + j];

    #pragma unroll
    for (int i = 0; i < 8; i++) {
        int row = bm + ty * 8 + i;
        if (row < M) {
            float* cptr = Cout + (size_t)row * 256 + bn + tx * 8;
            float4 o0, o1;
            o0.x = acc[i][0] + bb[0]; o0.y = acc[i][1] + bb[1];
            o0.z = acc[i][2] + bb[2]; o0.w = acc[i][3] + bb[3];
            o1.x = acc[i][4] + bb[4]; o1.y = acc[i][5] + bb[5];
            o1.z = acc[i][6] + bb[6]; o1.w = acc[i][7] + bb[7];
            *(float4*)(cptr)     = o0;
            *(float4*)(cptr + 4) = o1;
        }
    }
}

// ---------------- P GEMM: P[n,h,i] = sum_c q[n,h*32+c] * We[i,h*32+c] -------
// grid (ceil(N/64), 8). block 256. per-thread 8 nodes x 8 i.
__global__ __launch_bounds__(256)
void k_pgemm(const float* __restrict__ We) {
    __shared__ float qs[64][33];
    __shared__ float Wt[32][257];
    int h  = blockIdx.y;
    int n0 = blockIdx.x * 64;
    int t  = threadIdx.x;

    // load q slice [64 nodes][32 c]
    for (int idx = t; idx < 64 * 32; idx += 256) {
        int node = idx >> 5, c = idx & 31;
        int n = n0 + node;
        qs[node][c] = (n < NN) ? g_q[(size_t)n * 256 + h * 32 + c] : 0.f;
    }
    // load We slice transposed: Wt[c][i] = We[i*256 + h*32 + c]
    for (int idx = t; idx < 256 * 32; idx += 256) {
        int i = idx >> 5, c = idx & 31;
        Wt[c][i] = We[(size_t)i * 256 + h * 32 + c];
    }
    __syncthreads();

    int tx = t & 31;          // i = tx + ii*32
    int ty = t >> 5;          // nodes ty*8 .. ty*8+7
    float acc[8][8];
    #pragma unroll
    for (int r = 0; r < 8; r++)
        #pragma unroll
        for (int ii = 0; ii < 8; ii++) acc[r][ii] = 0.f;

    #pragma unroll 4
    for (int c = 0; c < 32; c++) {
        float a[8], b[8];
        #pragma unroll
        for (int r = 0; r < 8; r++) a[r] = qs[ty * 8 + r][c];
        #pragma unroll
        for (int ii = 0; ii < 8; ii++) b[ii] = Wt[c][tx + ii * 32];
        #pragma unroll
        for (int r = 0; r < 8; r++)
            #pragma unroll
            for (int ii = 0; ii < 8; ii++)
                acc[r][ii] = fmaf(a[r], b[ii], acc[r][ii]);
    }

    #pragma unroll
    for (int r = 0; r < 8; r++) {
        int n = n0 + ty * 8 + r;
        if (n < NN) {
            float* Pr = g_P + ((size_t)n * 8 + h) * 256;
            #pragma unroll
            for (int ii = 0; ii < 8; ii++)
                Pr[tx + ii * 32] = acc[r][ii];
        }
    }
}

// ---------------- edge pass: online softmax, A/vacc accumulation ------------
__global__ __launch_bounds__(256)
void k_edge(const float* __restrict__ ea, float* __restrict__ out) {
    __shared__ float eas[256];
    int n    = blockIdx.x;
    int h    = threadIdx.x >> 5;
    int lane = threadIdx.x & 31;

    int begin = g_off[n], end = g_off[n + 1];
    size_t nb = (size_t)n * 256 + h * 32 + lane;
    const float scale = 0.17677669529663687f;     // 1/sqrt(32)
    float qv = g_q[nb] * scale;

    const float* Pr = g_P + ((size_t)n * 8 + h) * 256;
    float preg[8];
    #pragma unroll
    for (int j = 0; j < 8; j++) preg[j] = __ldcs(Pr + j * 32 + lane) * scale;

    float m = -INFINITY, l = 0.f, vacc = 0.f;
    float A[8];
    #pragma unroll
    for (int j = 0; j < 8; j++) A[j] = 0.f;

    for (int idx = begin; idx < end; idx++) {
        int src = g_srcs[idx];
        int eo  = g_perm[idx];
        __syncthreads();
        eas[threadIdx.x] = __ldcs(ea + (size_t)eo * 256 + threadIdx.x);
        __syncthreads();

        size_t sb = (size_t)src * 256 + h * 32 + lane;
        float kv = g_k[sb];
        float vv = g_v[sb];
        float er[8];
        #pragma unroll
        for (int j = 0; j < 8; j++) er[j] = eas[j * 32 + lane];

        float s = qv * kv;
        #pragma unroll
        for (int j = 0; j < 8; j++) s = fmaf(preg[j], er[j], s);
        #pragma unroll
        for (int o = 16; o; o >>= 1) s += __shfl_xor_sync(0xffffffffu, s, o);

        float nm = fmaxf(m, s);
        float cf = __expf(m - nm);
        float p  = __expf(s - nm);
        l    = l * cf + p;
        vacc = vacc * cf + p * vv;
        #pragma unroll
        for (int j = 0; j < 8; j++) A[j] = A[j] * cf + p * er[j];
        m = nm;
    }

    float inv = (l > 0.f) ? (1.f / l) : 0.f;
    out[nb] += vacc * inv;
    float* Ar = g_A + ((size_t)n * 8 + h) * 256;
    #pragma unroll
    for (int j = 0; j < 8; j++) Ar[j * 32 + lane] = A[j] * inv;
}

// ---------------- A GEMM: out[n,h*32+c] += sum_i A[n,h,i] * We[i,h*32+c] ----
// grid (ceil(N/64), 8). block 256. per-thread 8 nodes x 1 c. K chunks of 64.
__global__ __launch_bounds__(256)
void k_agemm(const float* __restrict__ We, float* __restrict__ out) {
    __shared__ float As[64][65];
    __shared__ float Ws[64][33];
    int h  = blockIdx.y;
    int n0 = blockIdx.x * 64;
    int t  = threadIdx.x;
    int tx = t & 31;          // c
    int ty = t >> 5;          // node group

    float acc[8];
    #pragma unroll
    for (int r = 0; r < 8; r++) acc[r] = 0.f;

    for (int k0 = 0; k0 < 256; k0 += 64) {
        __syncthreads();
        // load A tile [64 nodes][64 k]
        for (int idx = t; idx < 64 * 64; idx += 256) {
            int node = idx >> 6, kk = idx & 63;
            int n = n0 + node;
            As[node][kk] = (n < NN)
                ? __ldcs(g_A + ((size_t)n * 8 + h) * 256 + k0 + kk) : 0.f;
        }
        // load We chunk: Ws[kk][c] = We[(k0+kk)*256 + h*32 + c]
        for (int idx = t; idx < 64 * 32; idx += 256) {
            int kk = idx >> 5, c = idx & 31;
            Ws[kk][c] = We[(size_t)(k0 + kk) * 256 + h * 32 + c];
        }
        __syncthreads();
        #pragma unroll 8
        for (int kk = 0; kk < 64; kk++) {
            float b = Ws[kk][tx];
            #pragma unroll
            for (int r = 0; r < 8; r++)
                acc[r] = fmaf(As[ty * 8 + r][kk], b, acc[r]);
        }
    }

    #pragma unroll
    for (int r = 0; r < 8; r++) {
        int n = n0 + ty * 8 + r;
        if (n < NN)
            out[(size_t)n * 256 + h * 32 + tx] += acc[r];
    }
}

// ---------------- launch ----------------------------------------------------
extern "C" void kernel_launch(void* const* d_in, const int* in_sizes, int n_in,
                              void* d_out, int out_size) {
    const float* x  = (const float*)d_in[0];
    const void*  ei = d_in[1];
    const float* ea = (const float*)d_in[2];
    const float* Wq = (const float*)d_in[3];
    const float* bq = (const float*)d_in[4];
    const float* Wk = (const float*)d_in[5];
    const float* bk = (const float*)d_in[6];
    const float* Wv = (const float*)d_in[7];
    const float* bv = (const float*)d_in[8];
    const float* We = (const float*)d_in[9];
    const float* Ws = (const float*)d_in[10];
    const float* bs = (const float*)d_in[11];
    float* out = (float*)d_out;

    // 0) sniff edge_index dtype
    k_detect<<<1, 32>>>((const long long*)ei);

    // 1) CSR sort by destination
    k_zero_deg<<<(NN + 255) / 256, 256>>>();
    k_hist<<<(EE + 255) / 256, 256>>>(ei);
    k_scan1<<<NB_SCAN, 1024>>>();
    k_scan2<<<1, 32>>>();
    k_scan3<<<(NN + 255) / 256, 256>>>();
    k_scatter<<<(EE + 255) / 256, 256>>>(ei);

    // 2) node GEMMs: q, k, v; skip (x@Ws+bs) straight into out
    dim3 gn((NN + 127) / 128, 2);
    k_sgemm<<<gn, 256>>>(x, Wq, bq, out, 0, NN);
    k_sgemm<<<gn, 256>>>(x, Wk, bk, out, 1, NN);
    k_sgemm<<<gn, 256>>>(x, Wv, bv, out, 2, NN);
    k_sgemm<<<gn, 256>>>(x, Ws, bs, out, 3, NN);

    // 3) P[n,h,i] = We_h @ q_h  (score projection)
    dim3 gp((NN + 63) / 64, 8);
    k_pgemm<<<gp, 256>>>(We);

    // 4) edge pass: scores via ea.P, online softmax, accumulate vacc and A
    k_edge<<<NN, 256>>>(ea, out);

    // 5) out += A @ We (per head slice)
    k_agemm<<<gp, 256>>>(We, out);
}